// round 7
// baseline (speedup 1.0000x reference)
#include <cuda_runtime.h>
#include <cstdint>

// probs: float32 [50,50,50,50] -> 6,250,000 floats (row-major)
// X:     int32   [8,000,000, 4]
// out:   float32 [8,000,000]
//
// out[i] = probs[ ((X0*50 + X1)*50 + X2)*50 + X3 ]
//
// Persistent blocks with DOUBLE-BUFFERED bulk-TMA prefetch of the X stream:
// while the block gathers from buffer s, the next tile's TMA is in flight
// into buffer s^1. X-fetch latency is fully hidden; L1tex sees an (almost)
// pure gather stream; gathers stay L2-only (__ldcg); stores are streaming.

constexpr int THREADS = 256;
constexpr int UNROLL  = 4;
constexpr int TILE    = THREADS * UNROLL;   // 1024 samples = 16 KB per buffer
constexpr int NBUF    = 2;

__device__ __forceinline__ void tma_1d(unsigned dst, const void* src,
                                       unsigned bytes, unsigned mbar)
{
    asm volatile(
        "cp.async.bulk.shared::cta.global.mbarrier::complete_tx::bytes "
        "[%0], [%1], %2, [%3];"
        :: "r"(dst), "l"(src), "r"(bytes), "r"(mbar) : "memory");
}

__device__ __forceinline__ void mbar_expect_tx(unsigned mbar, unsigned bytes)
{
    asm volatile("mbarrier.arrive.expect_tx.shared.b64 _, [%0], %1;"
                 :: "r"(mbar), "r"(bytes) : "memory");
}

__device__ __forceinline__ void mbar_wait(unsigned mbar, unsigned phase)
{
    unsigned done;
    do {
        asm volatile(
            "{\n\t.reg .pred p;\n\t"
            "mbarrier.try_wait.parity.acquire.cta.shared::cta.b64 p, [%1], %2, 0x989680;\n\t"
            "selp.b32 %0, 1, 0, p;\n\t}"
            : "=r"(done) : "r"(mbar), "r"(phase) : "memory");
    } while (!done);
}

__global__ __launch_bounds__(THREADS) void joint_cat_pipe(
    const float* __restrict__ probs,
    const int4* __restrict__ X,
    float* __restrict__ out,
    int n, int ntiles)
{
    __shared__ alignas(128) int4 xs[NBUF][TILE];
    __shared__ alignas(8) unsigned long long mbar_store[NBUF];

    int tid = threadIdx.x;
    unsigned mb[NBUF];
    unsigned xa[NBUF];
#pragma unroll
    for (int b = 0; b < NBUF; b++) {
        mb[b] = (unsigned)__cvta_generic_to_shared(&mbar_store[b]);
        xa[b] = (unsigned)__cvta_generic_to_shared(&xs[b][0]);
    }

    if (tid == 0) {
#pragma unroll
        for (int b = 0; b < NBUF; b++)
            asm volatile("mbarrier.init.shared.b64 [%0], 1;"
                         :: "r"(mb[b]) : "memory");
    }
    __syncthreads();

    const int stride = gridDim.x;

    // Prologue: prefetch up to NBUF tiles.
    if (tid == 0) {
#pragma unroll
        for (int s = 0; s < NBUF; s++) {
            long long t = blockIdx.x + (long long)s * stride;
            if (t < ntiles) {
                long long base = t * TILE;
                int cnt = n - (int)base; if (cnt > TILE) cnt = TILE;
                unsigned bytes = (unsigned)cnt * 16u;
                mbar_expect_tx(mb[s], bytes);
                tma_1d(xa[s], X + base, bytes, mb[s]);
            }
        }
    }

    int lane_group = (tid & 31) >> 3;   // quarter-warp gather issue
    int ph[NBUF] = {0, 0};

    int s = 0;
    for (long long t = blockIdx.x; t < ntiles; t += stride, s ^= 1) {
        long long base = t * TILE;
        int cnt = n - (int)base; if (cnt > TILE) cnt = TILE;

        mbar_wait(mb[s], ph[s]);
        ph[s] ^= 1;

        if (cnt == TILE) {
            int4 x[UNROLL];
#pragma unroll
            for (int k = 0; k < UNROLL; k++)
                x[k] = xs[s][k * THREADS + tid];

            int idx[UNROLL];
#pragma unroll
            for (int k = 0; k < UNROLL; k++)
                idx[k] = ((x[k].x * 50 + x[k].y) * 50 + x[k].z) * 50 + x[k].w;

            float r[UNROLL];
#pragma unroll
            for (int j = 0; j < 4; j++) {
#pragma unroll
                for (int k = 0; k < UNROLL; k++) {
                    if (lane_group == j)
                        r[k] = __ldcg(probs + idx[k]);   // L2-only gather
                }
            }

#pragma unroll
            for (int k = 0; k < UNROLL; k++)
                __stcs(&out[base + k * THREADS + tid], r[k]);
        } else {
#pragma unroll
            for (int k = 0; k < UNROLL; k++) {
                int j = k * THREADS + tid;
                if (j < cnt) {
                    int4 x = xs[s][j];
                    int idx = ((x.x * 50 + x.y) * 50 + x.z) * 50 + x.w;
                    __stcs(&out[base + j], __ldcg(probs + idx));
                }
            }
        }

        __syncthreads();   // everyone done reading xs[s] before refill

        long long tnext = t + (long long)NBUF * stride;
        if (tnext < ntiles && tid == 0) {
            long long b2 = tnext * TILE;
            int c2 = n - (int)b2; if (c2 > TILE) c2 = TILE;
            unsigned bytes = (unsigned)c2 * 16u;
            mbar_expect_tx(mb[s], bytes);
            tma_1d(xa[s], X + b2, bytes, mb[s]);
        }
    }
}

extern "C" void kernel_launch(void* const* d_in, const int* in_sizes, int n_in,
                              void* d_out, int out_size)
{
    const float* probs = (const float*)d_in[0];
    const int4* X = (const int4*)d_in[1];
    float* out = (float*)d_out;

    int n = out_size;                              // 8,000,000 samples
    int ntiles = (n + TILE - 1) / TILE;            // 7813
    int blocks = 148 * 6;                          // persistent: ~6 blocks/SM (32KB smem each)
    if (blocks > ntiles) blocks = ntiles;
    joint_cat_pipe<<<blocks, THREADS>>>(probs, X, out, n, ntiles);
}

// round 8
// speedup vs baseline: 1.5471x; 1.5471x over previous
#include <cuda_runtime.h>
#include <cstdint>

// probs: float32 [50,50,50,50] -> 6,250,000 floats (row-major)
// X:     int32   [8,000,000, 4]
// out:   float32 [8,000,000]
//
// out[i] = probs[ ((X0*50 + X1)*50 + X2)*50 + X3 ]
//
// Gathers are issued via cp.async (LDGSTS, 4B) into SMEM instead of LDG:
// completion is tracked in bulk by cp.async groups, not per-load MSHR /
// scoreboard slots, so the number of outstanding gather misses is no longer
// capped by the LSU's miss-tracking pool. Each warp reads its results back
// with conflict-free LDS and streams them out.

constexpr int THREADS = 256;
constexpr int UNROLL  = 8;
constexpr int TILE    = THREADS * UNROLL;   // 2048 samples per block

__device__ __forceinline__ void cp_async_4(unsigned smem_dst, const float* gmem_src)
{
    asm volatile("cp.async.ca.shared.global [%0], [%1], 4;"
                 :: "r"(smem_dst), "l"(gmem_src) : "memory");
}

__global__ __launch_bounds__(THREADS) void joint_cat_cpasync(
    const float* __restrict__ probs,
    const int4* __restrict__ X,
    float* __restrict__ out,
    int n)
{
    __shared__ float buf[TILE];   // 8 KB; thread's slot for batch k: buf[k*THREADS+tid]

    int tid = threadIdx.x;
    int base = blockIdx.x * TILE + tid;
    unsigned buf_base = (unsigned)__cvta_generic_to_shared(buf)
                      + (unsigned)tid * 4u;

    if (base + (UNROLL - 1) * THREADS < n) {
        // ---- fast path ----
        int4 x[UNROLL];
#pragma unroll
        for (int k = 0; k < UNROLL; k++)
            x[k] = __ldcs(&X[base + k * THREADS]);       // coalesced streaming 16B loads

#pragma unroll
        for (int k = 0; k < UNROLL; k++) {
            int idx = ((x[k].x * 50 + x[k].y) * 50 + x[k].z) * 50 + x[k].w;
            cp_async_4(buf_base + (unsigned)(k * THREADS) * 4u, probs + idx);
        }
        asm volatile("cp.async.commit_group;" ::: "memory");
        asm volatile("cp.async.wait_group 0;" ::: "memory");

#pragma unroll
        for (int k = 0; k < UNROLL; k++)
            __stcs(&out[base + k * THREADS], buf[k * THREADS + tid]);
    } else {
        // ---- tail ----
#pragma unroll
        for (int k = 0; k < UNROLL; k++) {
            int i = base + k * THREADS;
            if (i < n) {
                int4 x = __ldcs(&X[i]);
                int idx = ((x.x * 50 + x.y) * 50 + x.z) * 50 + x.w;
                cp_async_4(buf_base + (unsigned)(k * THREADS) * 4u, probs + idx);
            }
        }
        asm volatile("cp.async.commit_group;" ::: "memory");
        asm volatile("cp.async.wait_group 0;" ::: "memory");

#pragma unroll
        for (int k = 0; k < UNROLL; k++) {
            int i = base + k * THREADS;
            if (i < n)
                __stcs(&out[i], buf[k * THREADS + tid]);
        }
    }
}

extern "C" void kernel_launch(void* const* d_in, const int* in_sizes, int n_in,
                              void* d_out, int out_size)
{
    const float* probs = (const float*)d_in[0];
    const int4* X = (const int4*)d_in[1];
    float* out = (float*)d_out;

    int n = out_size;  // 8,000,000 samples
    int blocks = (n + TILE - 1) / TILE;
    joint_cat_cpasync<<<blocks, THREADS>>>(probs, X, out, n);
}